// round 1
// baseline (speedup 1.0000x reference)
#include <cuda_runtime.h>

namespace {

constexpr int Bn = 2, Ln = 2048, Hn = 16, En = 64;
constexpr int BM = 64, BN = 64;
constexpr int ROWSTRIDE = Hn * En;  // floats between consecutive sequence positions

// Load a 64x64 fp32 tile (rows = seq positions starting at s0) into 4 float4 regs/thread.
// Thread t, chunk u -> flat float4 id f = t + 256u; row = f>>4, col4 = f&15.
__device__ __forceinline__ void load_tile64(float4 (&reg)[4], const float* __restrict__ base,
                                            int s0) {
  const int t = threadIdx.x;
#pragma unroll
  for (int u = 0; u < 4; u++) {
    int f = t + 256 * u;
    int r = f >> 4;
    int c = f & 15;
    reg[u] = *reinterpret_cast<const float4*>(base + (size_t)(s0 + r) * ROWSTRIDE + 4 * c);
  }
}

__global__ void __launch_bounds__(256, 2)
attn_fwd(const float* __restrict__ Q, const float* __restrict__ K,
         const float* __restrict__ V, float* __restrict__ O) {
  // Reverse qt so the heaviest (longest) q-tiles are scheduled first.
  const int qt = (int)gridDim.x - 1 - (int)blockIdx.x;
  const int h = blockIdx.y;
  const int b = blockIdx.z;
  const int q0 = qt * BM;

  // Qs: Q^T [e][r] swizzled. Ks: K^T [e][k] swizzled, reused as P^T [k][r] swizzled.
  // Vs: V [k][e] row-major.
  __shared__ float4 Qs4[64 * 16];
  __shared__ float4 Ks4[64 * 16];
  __shared__ float4 Vs4[64 * 16];
  float* const Qs = reinterpret_cast<float*>(Qs4);
  float* const Ks = reinterpret_cast<float*>(Ks4);

  const int t = threadIdx.x;
  const int ty = t >> 4;  // 0..15: owns rows 4*ty..4*ty+3
  const int tx = t & 15;  // 0..15: owns cols 4*tx..4*tx+3

  const float* Qg = Q + ((size_t)(b * Ln + q0) * Hn + h) * En;
  const float* Kg = K + ((size_t)(b * Ln) * Hn + h) * En;
  const float* Vg = V + ((size_t)(b * Ln) * Hn + h) * En;
  float* Og = O + ((size_t)(b * Ln + q0) * Hn + h) * En;

  // ---- Load Q tile, scale by 1/sqrt(64), store transposed + swizzled ----
  {
#pragma unroll
    for (int u = 0; u < 4; u++) {
      int f = t + 256 * u;
      int r = f >> 4;
      int c = f & 15;
      float4 v = *reinterpret_cast<const float4*>(Qg + (size_t)r * ROWSTRIDE + 4 * c);
      float vv[4] = {v.x * 0.125f, v.y * 0.125f, v.z * 0.125f, v.w * 0.125f};
#pragma unroll
      for (int i = 0; i < 4; i++) {
        int e = 4 * c + i;
        int pc = (r >> 2) ^ (c & 7);  // swizzled col4
        Qs[e * 64 + pc * 4 + (r & 3)] = vv[i];
      }
    }
  }

  // ---- Prefetch first K/V tile into registers ----
  float4 kreg[4], vreg[4];
  load_tile64(kreg, Kg, 0);
  load_tile64(vreg, Vg, 0);

  float m_i[4], l_i[4], acc[4][4];
#pragma unroll
  for (int i = 0; i < 4; i++) {
    m_i[i] = -1e30f;
    l_i[i] = 0.0f;
#pragma unroll
    for (int j = 0; j < 4; j++) acc[i][j] = 0.0f;
  }

  for (int kt = 0; kt <= qt; kt++) {
    __syncthreads();  // prior iteration done reading Ks(P)/Vs

    // ---- Stage K (transposed+swizzled) and V (row-major) into SMEM ----
#pragma unroll
    for (int u = 0; u < 4; u++) {
      int f = t + 256 * u;
      int r = f >> 4;  // key index within tile
      int c = f & 15;
      float vv[4] = {kreg[u].x, kreg[u].y, kreg[u].z, kreg[u].w};
#pragma unroll
      for (int i = 0; i < 4; i++) {
        int e = 4 * c + i;
        int pc = (r >> 2) ^ (c & 7);
        Ks[e * 64 + pc * 4 + (r & 3)] = vv[i];
      }
      Vs4[r * 16 + c] = vreg[u];
    }
    __syncthreads();

    // Prefetch next tile while we compute on this one.
    if (kt < qt) {
      load_tile64(kreg, Kg, (kt + 1) * BN);
      load_tile64(vreg, Vg, (kt + 1) * BN);
    }

    // ---- S = (Q*scale) K^T : 4x4 micro-tile per thread ----
    float s[4][4];
#pragma unroll
    for (int i = 0; i < 4; i++)
#pragma unroll
      for (int j = 0; j < 4; j++) s[i][j] = 0.0f;

#pragma unroll 16
    for (int e = 0; e < 64; e++) {
      int sw = (e >> 2) & 7;
      float4 qf = Qs4[e * 16 + (ty ^ sw)];
      float4 kf = Ks4[e * 16 + (tx ^ sw)];
      float qa[4] = {qf.x, qf.y, qf.z, qf.w};
      float ka[4] = {kf.x, kf.y, kf.z, kf.w};
#pragma unroll
      for (int i = 0; i < 4; i++)
#pragma unroll
        for (int j = 0; j < 4; j++) s[i][j] = fmaf(qa[i], ka[j], s[i][j]);
    }

    // ---- Causal mask (only the diagonal tile needs it; q0 == k0 there) ----
    if (kt == qt) {
#pragma unroll
      for (int i = 0; i < 4; i++)
#pragma unroll
        for (int j = 0; j < 4; j++)
          if (4 * tx + j > 4 * ty + i) s[i][j] = -1e30f;
    }

    // ---- Online softmax (row reductions over the 16 tx-threads via shfl) ----
    float corr[4];
#pragma unroll
    for (int i = 0; i < 4; i++) {
      float m0 = fmaxf(fmaxf(s[i][0], s[i][1]), fmaxf(s[i][2], s[i][3]));
#pragma unroll
      for (int off = 8; off >= 1; off >>= 1)
        m0 = fmaxf(m0, __shfl_xor_sync(0xffffffffu, m0, off));
      float mn = fmaxf(m_i[i], m0);
      corr[i] = __expf(m_i[i] - mn);
      m_i[i] = mn;
      float rs = 0.0f;
#pragma unroll
      for (int j = 0; j < 4; j++) {
        s[i][j] = __expf(s[i][j] - mn);
        rs += s[i][j];
      }
#pragma unroll
      for (int off = 8; off >= 1; off >>= 1)
        rs += __shfl_xor_sync(0xffffffffu, rs, off);
      l_i[i] = l_i[i] * corr[i] + rs;
#pragma unroll
      for (int j = 0; j < 4; j++) acc[i][j] *= corr[i];
    }

    __syncthreads();  // everyone finished reading Ks before it becomes P^T

    // ---- Write P transposed+swizzled into the Ks buffer ----
#pragma unroll
    for (int j = 0; j < 4; j++) {
      int k = 4 * tx + j;
      int pc = ty ^ (tx & 7);
      Ks4[k * 16 + pc] = make_float4(s[0][j], s[1][j], s[2][j], s[3][j]);
    }
    __syncthreads();

    // ---- O += P V : 4x4 micro-tile per thread ----
#pragma unroll 16
    for (int k = 0; k < 64; k++) {
      int sw = (k >> 2) & 7;
      float4 pf = Ks4[k * 16 + (ty ^ sw)];
      float4 vf = Vs4[k * 16 + tx];
      float pa[4] = {pf.x, pf.y, pf.z, pf.w};
      float va[4] = {vf.x, vf.y, vf.z, vf.w};
#pragma unroll
      for (int i = 0; i < 4; i++)
#pragma unroll
        for (int c = 0; c < 4; c++) acc[i][c] = fmaf(pa[i], va[c], acc[i][c]);
    }
  }

  // ---- Epilogue: normalize and store ----
#pragma unroll
  for (int i = 0; i < 4; i++) {
    float inv = 1.0f / l_i[i];
    float4 o = make_float4(acc[i][0] * inv, acc[i][1] * inv, acc[i][2] * inv, acc[i][3] * inv);
    *reinterpret_cast<float4*>(Og + (size_t)(4 * ty + i) * ROWSTRIDE + 4 * tx) = o;
  }
}

}  // namespace

extern "C" void kernel_launch(void* const* d_in, const int* in_sizes, int n_in,
                              void* d_out, int out_size) {
  (void)in_sizes; (void)n_in; (void)out_size;
  const float* Q = (const float*)d_in[0];
  const float* K = (const float*)d_in[1];
  const float* V = (const float*)d_in[2];
  float* O = (float*)d_out;

  dim3 grid(Ln / BM, Hn, Bn);  // (32 q-tiles, 16 heads, 2 batches)
  attn_fwd<<<grid, 256>>>(Q, K, V, O);
}